// round 12
// baseline (speedup 1.0000x reference)
#include <cuda_runtime.h>
#include <cuda_bf16.h>
#include <math.h>
#include <stdint.h>

// Problem constants (fixed shapes)
#define NN 10000
#define EE 128000
#define CC 128
#define AA 10
#define FF 8
#define MID 1152                       // C * 9
#define SC_OFF (2 * NN * MID)

// msg internal layout per z: [ l0: N*1*C | l1: N*3*C | l2: N*5*C ]
#define ZSZ   (NN * 9 * CC)
#define L0OFF 0
#define L1OFF (NN * CC)
#define L2OFF (4 * NN * CC)

typedef __nv_bfloat16 bf16;

// ---------------- scratch (static device globals) ---------------------------
__device__ __align__(128) float g_h[NN * CC];              // fp32 (gather input)
__device__ __align__(128) float g_tpw[(size_t)EE * 384];   // fp32 (gather input)
__device__ __align__(128) float g_tmp[2 * ZSZ];            // irreps GEMM output
// bf16 hi/lo operand pairs
__device__ __align__(128) bf16 g_nfh[NN * CC];
__device__ __align__(128) bf16 g_nfl[NN * CC];
__device__ __align__(128) bf16 g_efh[EE * 64];
__device__ __align__(128) bf16 g_efl[EE * 64];
__device__ __align__(128) bf16 g_yh[NN * CC * AA];
__device__ __align__(128) bf16 g_yl[NN * CC * AA];
__device__ __align__(128) bf16 g_tah[EE * 64];
__device__ __align__(128) bf16 g_tal[EE * 64];
__device__ __align__(128) bf16 g_tbh[EE * 64];
__device__ __align__(128) bf16 g_tbl[EE * 64];
__device__ __align__(128) bf16 g_msgh[2 * ZSZ];
__device__ __align__(128) bf16 g_msgl[2 * ZSZ];
__device__ __align__(128) bf16 g_wth[266240];
__device__ __align__(128) bf16 g_wtl[266240];
__device__ int   g_deg[NN + 8];
__device__ int   g_off[NN + 8];
__device__ int   g_pos[NN + 8];
__device__ int   g_eid[EE];

// transposed-weight offsets inside g_wt (all K padded to multiples of 64)
#define WUP_T 0
#define WSK_T 16384
#define W1_T  180224
#define W2_T  184320
#define W3_T  188416
#define W4_T  192512
#define WL0_T 217088
#define WL1_T 233472
#define WL2_T 249856
#define WT_TOTAL 266240

// ---------------- helpers ---------------------------------------------------
__device__ __forceinline__ uint32_t smem_to_u32(const void* p) {
    uint32_t a;
    asm("{ .reg .u64 t; cvta.to.shared.u64 t, %1; cvt.u32.u64 %0, t; }"
        : "=r"(a) : "l"(p));
    return a;
}

__device__ __forceinline__ void ldm_x4(uint32_t addr, uint32_t* r) {
    asm volatile("ldmatrix.sync.aligned.m8n8.x4.shared.b16 {%0,%1,%2,%3}, [%4];"
                 : "=r"(r[0]), "=r"(r[1]), "=r"(r[2]), "=r"(r[3]) : "r"(addr));
}

__device__ __forceinline__ void mma16816(float* d, const uint32_t* a,
                                         const uint32_t* b) {
    asm volatile("mma.sync.aligned.m16n8k16.row.col.f32.bf16.bf16.f32 "
                 "{%0,%1,%2,%3}, {%4,%5,%6,%7}, {%8,%9}, {%0,%1,%2,%3};"
                 : "+f"(d[0]), "+f"(d[1]), "+f"(d[2]), "+f"(d[3])
                 : "r"(a[0]), "r"(a[1]), "r"(a[2]), "r"(a[3]),
                   "r"(b[0]), "r"(b[1]));
}

#define CP16(dst, src) \
    asm volatile("cp.async.cg.shared.global [%0], [%1], 16;" \
                 :: "r"(dst), "l"(src) : "memory")
#define CP_COMMIT() asm volatile("cp.async.commit_group;" ::: "memory")
#define CP_WAIT0()  asm volatile("cp.async.wait_group 0;" ::: "memory")
#define CP_WAIT1()  asm volatile("cp.async.wait_group 1;" ::: "memory")

__device__ __forceinline__ void split1(float v, bf16& hi, bf16& lo)
{
    hi = __float2bfloat16_rn(v);
    lo = __float2bfloat16_rn(v - __bfloat162float(hi));
}

// ---------------- mma.sync bf16 pre-split GEMM, cp.async pipelined ----------
// C = act( A[MxK] @ Bt[Ncols x K]^T ).  A,B given as bf16 hi/lo pairs, lda=K.
// Block tile 128 x (64*NB), K-chunk 64, 8 warps (4m x 2n), warp tile 32 x 32*NB.
#define ROWB 144

template<int NB>
__global__ __launch_bounds__(256)
void tc_gemm_k(const bf16* __restrict__ Ah, const bf16* __restrict__ Al,
               const bf16* __restrict__ Bh, const bf16* __restrict__ Bl,
               float* __restrict__ Cf, bf16* __restrict__ Oh,
               bf16* __restrict__ Ol, int ldcr,
               int M, int K, int act)
{
    constexpr int BN = 64 * NB;
    constexpr int SA_H = 0;
    constexpr int SA_L = 128 * ROWB;
    constexpr int SB_H = 2 * 128 * ROWB;
    constexpr int SB_L = 2 * 128 * ROWB + BN * ROWB;
    constexpr int SSTG = 2 * 128 * ROWB + 2 * BN * ROWB;
    constexpr int BSH = (NB == 1) ? 9 : 10;   // log2(BN*8)

    extern __shared__ char smem[];
    const uint32_t sb = smem_to_u32(smem);
    const int tid = threadIdx.x;
    const int lane = tid & 31;
    const int wid = tid >> 5;
    const int wm = (wid & 3) * 32;
    const int wn = (wid >> 2) * 32 * NB;
    const int bm = blockIdx.y * 128;
    const int bn = blockIdx.x * BN;
    const int nchunks = K >> 6;

    float acc[2][4 * NB][4];
#pragma unroll
    for (int i = 0; i < 2; i++)
#pragma unroll
        for (int j = 0; j < 4 * NB; j++)
#pragma unroll
            for (int q = 0; q < 4; q++) acc[i][j][q] = 0.f;

    auto stage = [&](int ch) {
        const int k0 = ch << 6;
        const uint32_t stg = sb + (uint32_t)((ch & 1) * SSTG);
#pragma unroll
        for (int li = 0; li < 8; li++) {
            int u = tid + li * 256;
            int buf = u >> 10;
            int idx = u & 1023;
            int r = idx >> 3;
            int c = idx & 7;
            int gr = bm + r;
            if (gr >= M) gr = M - 1;      // clamp: garbage rows are discarded
            const bf16* src = (buf ? Al : Ah) + (size_t)gr * K + k0 + c * 8;
            uint32_t dst = stg + (buf ? SA_L : SA_H) + r * ROWB + c * 16;
            CP16(dst, src);
        }
#pragma unroll
        for (int li = 0; li < 4 * NB; li++) {
            int u = tid + li * 256;
            int buf = u >> BSH;
            int idx = u & ((1 << BSH) - 1);
            int r = idx >> 3;
            int c = idx & 7;
            const bf16* src = (buf ? Bl : Bh) + (size_t)(bn + r) * K + k0 + c * 8;
            uint32_t dst = stg + (buf ? SB_L : SB_H) + r * ROWB + c * 16;
            CP16(dst, src);
        }
        CP_COMMIT();
    };

    const uint32_t aRow = wm + (lane & 15);
    const uint32_t aKp = (lane >> 4) * 8;
    const uint32_t aOff0 = aRow * ROWB + aKp * 2;
    const uint32_t aOff1 = (aRow + 16) * ROWB + aKp * 2;
    const uint32_t bRow = (lane & 7) + ((lane >> 4) * 8);
    const uint32_t bKp = ((lane >> 3) & 1) * 8;
    uint32_t bOffs[2 * NB];
#pragma unroll
    for (int g = 0; g < 2 * NB; g++)
        bOffs[g] = (wn + g * 16 + bRow) * ROWB + bKp * 2;

    stage(0);

    for (int ch = 0; ch < nchunks; ch++) {
        if (ch + 1 < nchunks) {
            stage(ch + 1);
            CP_WAIT1();
        } else {
            CP_WAIT0();
        }
        __syncthreads();
        const uint32_t stg = sb + (uint32_t)((ch & 1) * SSTG);

#pragma unroll
        for (int ks = 0; ks < 4; ks++) {
            const uint32_t k2 = (uint32_t)(ks * 32);
            uint32_t ah0[4], ah1[4], al0[4], al1[4];
            uint32_t bb[2 * NB][4];
            ldm_x4(stg + SA_H + aOff0 + k2, ah0);
            ldm_x4(stg + SA_H + aOff1 + k2, ah1);
#pragma unroll
            for (int g = 0; g < 2 * NB; g++)
                ldm_x4(stg + SB_H + bOffs[g] + k2, bb[g]);
            // hi * hi
#pragma unroll
            for (int g = 0; g < 2 * NB; g++)
#pragma unroll
                for (int h2 = 0; h2 < 2; h2++) {
                    mma16816(acc[0][g * 2 + h2], ah0, bb[g] + 2 * h2);
                    mma16816(acc[1][g * 2 + h2], ah1, bb[g] + 2 * h2);
                }
            // lo * hi
            ldm_x4(stg + SA_L + aOff0 + k2, al0);
            ldm_x4(stg + SA_L + aOff1 + k2, al1);
#pragma unroll
            for (int g = 0; g < 2 * NB; g++)
#pragma unroll
                for (int h2 = 0; h2 < 2; h2++) {
                    mma16816(acc[0][g * 2 + h2], al0, bb[g] + 2 * h2);
                    mma16816(acc[1][g * 2 + h2], al1, bb[g] + 2 * h2);
                }
            // hi * lo (overwrite B regs)
#pragma unroll
            for (int g = 0; g < 2 * NB; g++)
                ldm_x4(stg + SB_L + bOffs[g] + k2, bb[g]);
#pragma unroll
            for (int g = 0; g < 2 * NB; g++)
#pragma unroll
                for (int h2 = 0; h2 < 2; h2++) {
                    mma16816(acc[0][g * 2 + h2], ah0, bb[g] + 2 * h2);
                    mma16816(acc[1][g * 2 + h2], ah1, bb[g] + 2 * h2);
                }
        }
        __syncthreads();
    }

    // ---- epilogue ----
#pragma unroll
    for (int mt = 0; mt < 2; mt++) {
        int r0g = bm + wm + mt * 16 + (lane >> 2);
#pragma unroll
        for (int nt = 0; nt < 4 * NB; nt++) {
            int cg = bn + wn + nt * 8 + (lane & 3) * 2;
            float* d = acc[mt][nt];
#pragma unroll
            for (int half = 0; half < 2; half++) {
                int r = r0g + half * 8;
                if (r >= M) continue;
                float v0 = d[half * 2 + 0];
                float v1 = d[half * 2 + 1];
                if (act) {
                    v0 = v0 / (1.f + __expf(-v0));
                    v1 = v1 / (1.f + __expf(-v1));
                }
                size_t base = (size_t)r * ldcr + cg;
                if (Cf) {
                    Cf[base] = v0;
                    Cf[base + 1] = v1;
                }
                if (Oh) {
                    bf16 h0, l0, h1, l1;
                    split1(v0, h0, l0);
                    split1(v1, h1, l1);
                    Oh[base] = h0;
                    Ol[base] = l0;
                    Oh[base + 1] = h1;
                    Ol[base + 1] = l1;
                }
            }
        }
    }
}

#define SSTG1 (2 * 128 * ROWB + 2 * 64 * ROWB)
#define S_TOT1 (2 * SSTG1)                       // 110592
#define SSTG2 (2 * 128 * ROWB + 2 * 128 * ROWB)
#define S_TOT2 (2 * SSTG2)                       // 147456

// ---------------- fused weight transpose + bf16 split -----------------------
// seg 1 (W_skip) is remapped: K index j = v*128+u  (matches yprep layout)
#define TSEG 9
__global__ void transpose_all_k(const float* __restrict__ s0, const float* __restrict__ s1,
                                const float* __restrict__ s2, const float* __restrict__ s3,
                                const float* __restrict__ s4, const float* __restrict__ s5,
                                const float* __restrict__ s6, const float* __restrict__ s7,
                                const float* __restrict__ s8,
                                bf16* __restrict__ wth, bf16* __restrict__ wtl)
{
    const float* srcs[TSEG] = {s0, s1, s2, s3, s4, s5, s6, s7, s8};
    const int Ksrc[TSEG] = {128, 1280, 8, 64, 64, 64, 128, 128, 128};
    const int Kdst[TSEG] = {128, 1280, 64, 64, 64, 64, 128, 128, 128};
    const int Ns[TSEG]   = {128, 128, 64, 64, 64, 384, 128, 128, 128};
    const int bases[TSEG] = {WUP_T, WSK_T, W1_T, W2_T, W3_T, W4_T,
                             WL0_T, WL1_T, WL2_T};
    for (int i = blockIdx.x * blockDim.x + threadIdx.x; i < WT_TOTAL;
         i += gridDim.x * blockDim.x) {
        int seg = 0;
#pragma unroll
        for (int s = 1; s < TSEG; s++)
            if (i >= bases[s]) seg = s;
        int local = i - bases[seg];
        int K = Kdst[seg];
        int c = local / K;
        int k = local - c * K;
        float v;
        if (seg == 1) {
            // k = vA*128 + u ; src W_skip[u][vA][c] = s1[u*1280 + vA*128 + c]
            int vA = k >> 7;
            int u = k & 127;
            v = __ldg(&s1[(size_t)u * 1280 + vA * 128 + c]);
        } else {
            v = (k < Ksrc[seg]) ? __ldg(&srcs[seg][(size_t)k * Ns[seg] + c]) : 0.f;
        }
        bf16 hi, lo;
        split1(v, hi, lo);
        wth[i] = hi;
        wtl[i] = lo;
    }
}

// ---------------- fp32 -> bf16 hi/lo convert (with K padding) ---------------
__global__ void conv_split_k(const float* __restrict__ in, bf16* __restrict__ oh,
                             bf16* __restrict__ ol, int M, int Kin, int Kout)
{
    for (int i = blockIdx.x * blockDim.x + threadIdx.x; i < M * Kout;
         i += gridDim.x * blockDim.x) {
        int r = i / Kout;
        int k = i - r * Kout;
        float v = (k < Kin) ? __ldg(&in[(size_t)r * Kin + k]) : 0.f;
        bf16 hi, lo;
        split1(v, hi, lo);
        oh[i] = hi;
        ol[i] = lo;
    }
}

// ---------------- merge: tmp per-l coalesced -> out [n][c*9+jm] -------------
#define MPAD 132
__global__ void merge_k(const float* __restrict__ tmp, float* __restrict__ out)
{
    int n = blockIdx.x;
    int z = blockIdx.y;
    const float* t = tmp + (size_t)z * ZSZ;
    float* o = out + (size_t)z * NN * MID + (size_t)n * MID;
    __shared__ float s[9 * MPAD];
    int c = threadIdx.x;    // 128
    s[0 * MPAD + c] = t[L0OFF + (size_t)n * CC + c];
#pragma unroll
    for (int m = 0; m < 3; m++)
        s[(1 + m) * MPAD + c] = t[L1OFF + ((size_t)n * 3 + m) * CC + c];
#pragma unroll
    for (int m = 0; m < 5; m++)
        s[(4 + m) * MPAD + c] = t[L2OFF + ((size_t)n * 5 + m) * CC + c];
    __syncthreads();
#pragma unroll
    for (int it = 0; it < 9; it++) {
        int i = it * 128 + c;
        int cc = i / 9;
        int jm = i - cc * 9;
        o[i] = s[jm * MPAD + cc];
    }
}

// ---------------- y outer product: y[n, v*128+u], coalesced -----------------
__global__ void yprep_k(const float* __restrict__ feats,
                        const float* __restrict__ attrs,
                        bf16* __restrict__ yh, bf16* __restrict__ yl)
{
    int n = blockIdx.x;
    __shared__ float sf[CC];
    __shared__ float sa[AA];
    if (threadIdx.x < CC) sf[threadIdx.x] = feats[(size_t)n * CC + threadIdx.x];
    if (threadIdx.x < AA) sa[threadIdx.x] = attrs[(size_t)n * AA + threadIdx.x];
    __syncthreads();
#pragma unroll
    for (int i = threadIdx.x; i < CC * AA; i += 256) {
        int v = i >> 7;          // attr index
        int u = i & 127;         // channel
        float val = sf[u] * sa[v];
        bf16 hi, lo;
        split1(val, hi, lo);
        yh[(size_t)n * (CC * AA) + i] = hi;
        yl[(size_t)n * (CC * AA) + i] = lo;
    }
}

// ---------------- CSR build -------------------------------------------------
__global__ void zero_deg_k(int* deg, int n)
{
    int i = blockIdx.x * blockDim.x + threadIdx.x;
    if (i < n) deg[i] = 0;
}
__global__ void count_deg_k(const int* __restrict__ recv, int* deg, int e)
{
    int i = blockIdx.x * blockDim.x + threadIdx.x;
    if (i < e) atomicAdd(&deg[recv[i]], 1);
}
__global__ void scan_k(const int* __restrict__ deg, int* off, int* pos, int n)
{
    __shared__ int wsum[32];
    __shared__ int carry_s;
    const int tid = threadIdx.x;
    const int lane = tid & 31;
    const int w = tid >> 5;
    if (tid == 0) carry_s = 0;
    __syncthreads();
    for (int base = 0; base < n; base += 1024) {
        int i = base + tid;
        int v = (i < n) ? deg[i] : 0;
        int x = v;
#pragma unroll
        for (int st = 1; st < 32; st <<= 1) {
            int t = __shfl_up_sync(0xFFFFFFFF, x, st);
            if (lane >= st) x += t;
        }
        if (lane == 31) wsum[w] = x;
        __syncthreads();
        if (w == 0) {
            int ws = (lane < 32) ? wsum[lane] : 0;
#pragma unroll
            for (int st = 1; st < 32; st <<= 1) {
                int t = __shfl_up_sync(0xFFFFFFFF, ws, st);
                if (lane >= st) ws += t;
            }
            wsum[lane] = ws;
        }
        __syncthreads();
        int incl = x + (w > 0 ? wsum[w - 1] : 0) + carry_s;
        int excl = incl - v;
        if (i < n) { off[i] = excl; pos[i] = excl; }
        __syncthreads();
        if (tid == 1023) carry_s = incl;
        __syncthreads();
    }
    if (threadIdx.x == 0) off[n] = carry_s;
}
__global__ void fill_eid_k(const int* __restrict__ recv, int* pos, int* eid, int e)
{
    int i = blockIdx.x * blockDim.x + threadIdx.x;
    if (i < e) {
        int p = atomicAdd(&pos[recv[i]], 1);
        eid[p] = i;
    }
}

// ---------------- gather: TP + segment sum, bf16 hi/lo msg output -----------
__global__ void gather_k(const float* __restrict__ h,
                         const float* __restrict__ tpw,
                         const float* __restrict__ yr,
                         const float* __restrict__ yi,
                         const int* __restrict__ senders,
                         const int* __restrict__ off,
                         const int* __restrict__ eid,
                         bf16* __restrict__ msgh, bf16* __restrict__ msgl)
{
    int n = blockIdx.x;
    int c = threadIdx.x;   // 128 threads, one per channel
    float ar[9], ai[9];
#pragma unroll
    for (int j = 0; j < 9; j++) { ar[j] = 0.f; ai[j] = 0.f; }

    int e0 = __ldg(&off[n]);
    int e1 = __ldg(&off[n + 1]);
    for (int p = e0; p < e1; p++) {
        int e = __ldg(&eid[p]);
        int s = __ldg(&senders[e]);
        float hc = h[(size_t)s * CC + c];
        const float* tw = tpw + (size_t)e * 384;
        float xw0 = hc * tw[c];
        float xw1 = hc * tw[128 + c];
        float xw2 = hc * tw[256 + c];
        const float* er = yr + (size_t)e * 9;
        const float* ei = yi + (size_t)e * 9;
        ar[0] += xw0 * __ldg(&er[0]);
        ai[0] += xw0 * __ldg(&ei[0]);
#pragma unroll
        for (int m = 0; m < 3; m++) {
            ar[1 + m] += xw1 * __ldg(&er[1 + m]);
            ai[1 + m] += xw1 * __ldg(&ei[1 + m]);
        }
#pragma unroll
        for (int m = 0; m < 5; m++) {
            ar[4 + m] += xw2 * __ldg(&er[4 + m]);
            ai[4 + m] += xw2 * __ldg(&ei[4 + m]);
        }
    }

    // per-l contiguous layout, split to bf16 hi/lo
#pragma unroll
    for (int z = 0; z < 2; z++) {
        const float* a = z ? ai : ar;
        bf16* mh = msgh + (size_t)z * ZSZ;
        bf16* ml = msgl + (size_t)z * ZSZ;
        bf16 hi, lo;
        split1(a[0], hi, lo);
        mh[L0OFF + (size_t)n * CC + c] = hi;
        ml[L0OFF + (size_t)n * CC + c] = lo;
#pragma unroll
        for (int m = 0; m < 3; m++) {
            split1(a[1 + m], hi, lo);
            mh[L1OFF + ((size_t)n * 3 + m) * CC + c] = hi;
            ml[L1OFF + ((size_t)n * 3 + m) * CC + c] = lo;
        }
#pragma unroll
        for (int m = 0; m < 5; m++) {
            split1(a[4 + m], hi, lo);
            mh[L2OFF + ((size_t)n * 5 + m) * CC + c] = hi;
            ml[L2OFF + ((size_t)n * 5 + m) * CC + c] = lo;
        }
    }
}

// ---------------- launch ----------------------------------------------------
static inline float* symf(const void* sym)
{
    void* p = nullptr;
    cudaGetSymbolAddress(&p, sym);
    return (float*)p;
}
static inline bf16* symb(const void* sym)
{
    void* p = nullptr;
    cudaGetSymbolAddress(&p, sym);
    return (bf16*)p;
}
static inline int* symi(const void* sym)
{
    void* p = nullptr;
    cudaGetSymbolAddress(&p, sym);
    return (int*)p;
}

static inline void tc_gemm(const bf16* Ah, const bf16* Al,
                           const bf16* Bh, const bf16* Bl,
                           float* Cf, bf16* Oh, bf16* Ol, int ldcr,
                           int M, int Ncols, int K, int act)
{
    if (Ncols % 128 == 0) {
        dim3 grid(Ncols / 128, (M + 127) / 128);
        tc_gemm_k<2><<<grid, 256, S_TOT2>>>(Ah, Al, Bh, Bl, Cf, Oh, Ol, ldcr,
                                            M, K, act);
    } else {
        dim3 grid(Ncols / 64, (M + 127) / 128);
        tc_gemm_k<1><<<grid, 256, S_TOT1>>>(Ah, Al, Bh, Bl, Cf, Oh, Ol, ldcr,
                                            M, K, act);
    }
}

extern "C" void kernel_launch(void* const* d_in, const int* in_sizes, int n_in,
                              void* d_out, int out_size)
{
    const float* node_attrs = (const float*)d_in[0];
    const float* node_feats = (const float*)d_in[1];
    const float* yr         = (const float*)d_in[2];
    const float* yi         = (const float*)d_in[3];
    const float* edge_feats = (const float*)d_in[4];
    const int*   edge_index = (const int*)d_in[5];
    const float* W_up   = (const float*)d_in[6];
    const float* W_skip = (const float*)d_in[7];
    const float* W1     = (const float*)d_in[8];
    const float* W2     = (const float*)d_in[9];
    const float* W3     = (const float*)d_in[10];
    const float* W4     = (const float*)d_in[11];
    const float* Wl[3]  = { (const float*)d_in[12], (const float*)d_in[13],
                            (const float*)d_in[14] };
    float* out = (float*)d_out;

    static int smem_set = 0;
    if (!smem_set) {
        cudaFuncSetAttribute(tc_gemm_k<1>,
                             cudaFuncAttributeMaxDynamicSharedMemorySize, S_TOT1);
        cudaFuncSetAttribute(tc_gemm_k<2>,
                             cudaFuncAttributeMaxDynamicSharedMemorySize, S_TOT2);
        smem_set = 1;
    }

    float* hh   = symf(g_h);
    float* tpw  = symf(g_tpw);
    float* tmp  = symf(g_tmp);
    bf16* nfh = symb(g_nfh); bf16* nfl = symb(g_nfl);
    bf16* efh = symb(g_efh); bf16* efl = symb(g_efl);
    bf16* yh  = symb(g_yh);  bf16* yl  = symb(g_yl);
    bf16* tah = symb(g_tah); bf16* tal = symb(g_tal);
    bf16* tbh = symb(g_tbh); bf16* tbl = symb(g_tbl);
    bf16* msgh = symb(g_msgh); bf16* msgl = symb(g_msgl);
    bf16* wth = symb(g_wth); bf16* wtl = symb(g_wtl);
    int* deg = symi(g_deg);
    int* off = symi(g_off);
    int* pos = symi(g_pos);
    int* eid = symi(g_eid);

    const int* recv = edge_index + EE;
    const int* send = edge_index;

    // launch order chosen so the profiler's 4th launch = sc GEMM (NB=2, K=1280)
    yprep_k<<<NN, 256>>>(node_feats, node_attrs, yh, yl);                 // 1
    transpose_all_k<<<1040, 256>>>(W_up, W_skip, W1, W2, W3, W4,
                                   Wl[0], Wl[1], Wl[2], wth, wtl);        // 2
    conv_split_k<<<1024, 256>>>(node_feats, nfh, nfl, NN, CC, CC);        // 3
    // sc = y @ W_skip
    tc_gemm(yh, yl, wth + WSK_T, wtl + WSK_T, out + SC_OFF, nullptr, nullptr,
            CC, NN, CC, CC * AA, 0);                                      // 4
    conv_split_k<<<2048, 256>>>(edge_feats, efh, efl, EE, FF, 64);        // 5
    // CSR
    zero_deg_k<<<(NN + 255) / 256, 256>>>(deg, NN);
    count_deg_k<<<(EE + 255) / 256, 256>>>(recv, deg, EE);
    scan_k<<<1, 1024>>>(deg, off, pos, NN);
    fill_eid_k<<<(EE + 255) / 256, 256>>>(recv, pos, eid, EE);
    // h = node_feats @ W_up
    tc_gemm(nfh, nfl, wth + WUP_T, wtl + WUP_T, hh, nullptr, nullptr, CC,
            NN, CC, CC, 0);
    // edge MLP (bf16 hi/lo chain)
    tc_gemm(efh, efl, wth + W1_T, wtl + W1_T, nullptr, tah, tal, 64,
            EE, 64, 64, 1);
    tc_gemm(tah, tal, wth + W2_T, wtl + W2_T, nullptr, tbh, tbl, 64,
            EE, 64, 64, 1);
    tc_gemm(tbh, tbl, wth + W3_T, wtl + W3_T, nullptr, tah, tal, 64,
            EE, 64, 64, 1);
    tc_gemm(tah, tal, wth + W4_T, wtl + W4_T, tpw, nullptr, nullptr, 384,
            EE, 384, 64, 0);
    // tensor product + segment sum
    gather_k<<<NN, 128>>>(hh, tpw, yr, yi, send, off, eid, msgh, msgl);
    // fused per-l channel-mixing linears -> coalesced tmp (fp32)
    static const int ldim[3] = {1, 3, 5};
    static const int loff[3] = {L0OFF, L1OFF, L2OFF};
    static const int wlo[3] = {WL0_T, WL1_T, WL2_T};
    for (int z = 0; z < 2; z++) {
        for (int l = 0; l < 3; l++) {
            int d = ldim[l];
            const bf16* Amh = msgh + (size_t)z * ZSZ + loff[l];
            const bf16* Aml = msgl + (size_t)z * ZSZ + loff[l];
            float* Cm = tmp + (size_t)z * ZSZ + loff[l];
            tc_gemm(Amh, Aml, wth + wlo[l], wtl + wlo[l], Cm, nullptr, nullptr,
                    CC, NN * d, CC, CC, 0);
        }
    }
    // merge tmp -> out (coalesced both sides)
    merge_k<<<dim3(NN, 2), 128>>>(tmp, out);
}

// round 14
// speedup vs baseline: 1.0929x; 1.0929x over previous
#include <cuda_runtime.h>
#include <cuda_bf16.h>
#include <math.h>
#include <stdint.h>

// Problem constants (fixed shapes)
#define NN 10000
#define EE 128000
#define CC 128
#define AA 10
#define FF 8
#define MID 1152                       // C * 9
#define SC_OFF (2 * NN * MID)

// msg internal layout per z: [ l0: N*1*C | l1: N*3*C | l2: N*5*C ]
#define ZSZ   (NN * 9 * CC)
#define L0OFF 0
#define L1OFF (NN * CC)
#define L2OFF (4 * NN * CC)

typedef __nv_bfloat16 bf16;

// ---------------- scratch (static device globals) ---------------------------
__device__ __align__(128) float g_h[NN * CC];              // fp32 (gather input)
__device__ __align__(128) float g_tpw[(size_t)EE * 384];   // fp32, receiver-sorted
__device__ __align__(128) float g_ys[(size_t)EE * 18];     // sorted edge SH (r|i)
__device__ __align__(128) float g_tmp[2 * ZSZ];            // irreps GEMM output
// bf16 hi/lo operand pairs
__device__ __align__(128) bf16 g_nfh[NN * CC];
__device__ __align__(128) bf16 g_nfl[NN * CC];
__device__ __align__(128) bf16 g_efh[EE * 64];
__device__ __align__(128) bf16 g_efl[EE * 64];
__device__ __align__(128) bf16 g_yh[NN * CC * AA];
__device__ __align__(128) bf16 g_yl[NN * CC * AA];
__device__ __align__(128) bf16 g_tah[EE * 64];
__device__ __align__(128) bf16 g_tal[EE * 64];
__device__ __align__(128) bf16 g_tbh[EE * 64];
__device__ __align__(128) bf16 g_tbl[EE * 64];
__device__ __align__(128) bf16 g_msgh[2 * ZSZ];
__device__ __align__(128) bf16 g_msgl[2 * ZSZ];
__device__ __align__(128) bf16 g_wth[266240];
__device__ __align__(128) bf16 g_wtl[266240];
__device__ int   g_deg[NN + 8];
__device__ int   g_off[NN + 8];
__device__ int   g_pos[NN + 8];
__device__ int   g_eid[EE];
__device__ int   g_sperm[EE];

// transposed-weight offsets inside g_wt (all K padded to multiples of 64)
#define WUP_T 0
#define WSK_T 16384
#define W1_T  180224
#define W2_T  184320
#define W3_T  188416
#define W4_T  192512
#define WL0_T 217088
#define WL1_T 233472
#define WL2_T 249856
#define WT_TOTAL 266240

// ---------------- helpers ---------------------------------------------------
__device__ __forceinline__ uint32_t smem_to_u32(const void* p) {
    uint32_t a;
    asm("{ .reg .u64 t; cvta.to.shared.u64 t, %1; cvt.u32.u64 %0, t; }"
        : "=r"(a) : "l"(p));
    return a;
}

__device__ __forceinline__ void ldm_x4(uint32_t addr, uint32_t* r) {
    asm volatile("ldmatrix.sync.aligned.m8n8.x4.shared.b16 {%0,%1,%2,%3}, [%4];"
                 : "=r"(r[0]), "=r"(r[1]), "=r"(r[2]), "=r"(r[3]) : "r"(addr));
}

__device__ __forceinline__ void mma16816(float* d, const uint32_t* a,
                                         const uint32_t* b) {
    asm volatile("mma.sync.aligned.m16n8k16.row.col.f32.bf16.bf16.f32 "
                 "{%0,%1,%2,%3}, {%4,%5,%6,%7}, {%8,%9}, {%0,%1,%2,%3};"
                 : "+f"(d[0]), "+f"(d[1]), "+f"(d[2]), "+f"(d[3])
                 : "r"(a[0]), "r"(a[1]), "r"(a[2]), "r"(a[3]),
                   "r"(b[0]), "r"(b[1]));
}

#define CP16(dst, src) \
    asm volatile("cp.async.cg.shared.global [%0], [%1], 16;" \
                 :: "r"(dst), "l"(src) : "memory")
#define CP_COMMIT() asm volatile("cp.async.commit_group;" ::: "memory")
#define CP_WAIT0()  asm volatile("cp.async.wait_group 0;" ::: "memory")
#define CP_WAIT1()  asm volatile("cp.async.wait_group 1;" ::: "memory")

__device__ __forceinline__ void split1(float v, bf16& hi, bf16& lo)
{
    hi = __float2bfloat16_rn(v);
    lo = __float2bfloat16_rn(v - __bfloat162float(hi));
}

// ---------------- mma.sync bf16 pre-split GEMM body -------------------------
// C = act( A[MxK] @ Bt[Ncols x K]^T ).  A,B given as bf16 hi/lo pairs, lda=K.
// Block tile 128 x (64*NB), K-chunk 64, 8 warps (4m x 2n), warp tile 32 x 32*NB.
#define ROWB 144

template<int NB>
__device__ __forceinline__
void gemm_body(const bf16* __restrict__ Ah, const bf16* __restrict__ Al,
               const bf16* __restrict__ Bh, const bf16* __restrict__ Bl,
               float* __restrict__ Cf, bf16* __restrict__ Oh,
               bf16* __restrict__ Ol, int ldcr,
               int M, int K, int act, int bm, int bn, char* smem)
{
    constexpr int BN = 64 * NB;
    constexpr int SA_H = 0;
    constexpr int SA_L = 128 * ROWB;
    constexpr int SB_H = 2 * 128 * ROWB;
    constexpr int SB_L = 2 * 128 * ROWB + BN * ROWB;
    constexpr int SSTG = 2 * 128 * ROWB + 2 * BN * ROWB;
    constexpr int BSH = (NB == 1) ? 9 : 10;   // log2(BN*8)

    const uint32_t sb = smem_to_u32(smem);
    const int tid = threadIdx.x;
    const int lane = tid & 31;
    const int wid = tid >> 5;
    const int wm = (wid & 3) * 32;
    const int wn = (wid >> 2) * 32 * NB;
    const int nchunks = K >> 6;

    float acc[2][4 * NB][4];
#pragma unroll
    for (int i = 0; i < 2; i++)
#pragma unroll
        for (int j = 0; j < 4 * NB; j++)
#pragma unroll
            for (int q = 0; q < 4; q++) acc[i][j][q] = 0.f;

    auto stage = [&](int ch) {
        const int k0 = ch << 6;
        const uint32_t stg = sb + (uint32_t)((ch & 1) * SSTG);
#pragma unroll
        for (int li = 0; li < 8; li++) {
            int u = tid + li * 256;
            int buf = u >> 10;
            int idx = u & 1023;
            int r = idx >> 3;
            int c = idx & 7;
            int gr = bm + r;
            if (gr >= M) gr = M - 1;      // clamp: garbage rows are discarded
            const bf16* src = (buf ? Al : Ah) + (size_t)gr * K + k0 + c * 8;
            uint32_t dst = stg + (buf ? SA_L : SA_H) + r * ROWB + c * 16;
            CP16(dst, src);
        }
#pragma unroll
        for (int li = 0; li < 4 * NB; li++) {
            int u = tid + li * 256;
            int buf = u >> BSH;
            int idx = u & ((1 << BSH) - 1);
            int r = idx >> 3;
            int c = idx & 7;
            const bf16* src = (buf ? Bl : Bh) + (size_t)(bn + r) * K + k0 + c * 8;
            uint32_t dst = stg + (buf ? SB_L : SB_H) + r * ROWB + c * 16;
            CP16(dst, src);
        }
        CP_COMMIT();
    };

    const uint32_t aRow = wm + (lane & 15);
    const uint32_t aKp = (lane >> 4) * 8;
    const uint32_t aOff0 = aRow * ROWB + aKp * 2;
    const uint32_t aOff1 = (aRow + 16) * ROWB + aKp * 2;
    const uint32_t bRow = (lane & 7) + ((lane >> 4) * 8);
    const uint32_t bKp = ((lane >> 3) & 1) * 8;
    uint32_t bOffs[2 * NB];
#pragma unroll
    for (int g = 0; g < 2 * NB; g++)
        bOffs[g] = (wn + g * 16 + bRow) * ROWB + bKp * 2;

    stage(0);

    for (int ch = 0; ch < nchunks; ch++) {
        if (ch + 1 < nchunks) {
            stage(ch + 1);
            CP_WAIT1();
        } else {
            CP_WAIT0();
        }
        __syncthreads();
        const uint32_t stg = sb + (uint32_t)((ch & 1) * SSTG);

#pragma unroll
        for (int ks = 0; ks < 4; ks++) {
            const uint32_t k2 = (uint32_t)(ks * 32);
            uint32_t ah0[4], ah1[4], al0[4], al1[4];
            uint32_t bb[2 * NB][4];
            ldm_x4(stg + SA_H + aOff0 + k2, ah0);
            ldm_x4(stg + SA_H + aOff1 + k2, ah1);
#pragma unroll
            for (int g = 0; g < 2 * NB; g++)
                ldm_x4(stg + SB_H + bOffs[g] + k2, bb[g]);
#pragma unroll
            for (int g = 0; g < 2 * NB; g++)
#pragma unroll
                for (int h2 = 0; h2 < 2; h2++) {
                    mma16816(acc[0][g * 2 + h2], ah0, bb[g] + 2 * h2);
                    mma16816(acc[1][g * 2 + h2], ah1, bb[g] + 2 * h2);
                }
            ldm_x4(stg + SA_L + aOff0 + k2, al0);
            ldm_x4(stg + SA_L + aOff1 + k2, al1);
#pragma unroll
            for (int g = 0; g < 2 * NB; g++)
#pragma unroll
                for (int h2 = 0; h2 < 2; h2++) {
                    mma16816(acc[0][g * 2 + h2], al0, bb[g] + 2 * h2);
                    mma16816(acc[1][g * 2 + h2], al1, bb[g] + 2 * h2);
                }
#pragma unroll
            for (int g = 0; g < 2 * NB; g++)
                ldm_x4(stg + SB_L + bOffs[g] + k2, bb[g]);
#pragma unroll
            for (int g = 0; g < 2 * NB; g++)
#pragma unroll
                for (int h2 = 0; h2 < 2; h2++) {
                    mma16816(acc[0][g * 2 + h2], ah0, bb[g] + 2 * h2);
                    mma16816(acc[1][g * 2 + h2], ah1, bb[g] + 2 * h2);
                }
        }
        __syncthreads();
    }

    // ---- epilogue ----
#pragma unroll
    for (int mt = 0; mt < 2; mt++) {
        int r0g = bm + wm + mt * 16 + (lane >> 2);
#pragma unroll
        for (int nt = 0; nt < 4 * NB; nt++) {
            int cg = bn + wn + nt * 8 + (lane & 3) * 2;
            float* d = acc[mt][nt];
#pragma unroll
            for (int half = 0; half < 2; half++) {
                int r = r0g + half * 8;
                if (r >= M) continue;
                float v0 = d[half * 2 + 0];
                float v1 = d[half * 2 + 1];
                if (act) {
                    v0 = v0 / (1.f + __expf(-v0));
                    v1 = v1 / (1.f + __expf(-v1));
                }
                size_t base = (size_t)r * ldcr + cg;
                if (Cf) {
                    Cf[base] = v0;
                    Cf[base + 1] = v1;
                }
                if (Oh) {
                    bf16 h0, l0, h1, l1;
                    split1(v0, h0, l0);
                    split1(v1, h1, l1);
                    Oh[base] = h0;
                    Ol[base] = l0;
                    Oh[base + 1] = h1;
                    Ol[base + 1] = l1;
                }
            }
        }
    }
}

template<int NB>
__global__ __launch_bounds__(256)
void tc_gemm_k(const bf16* __restrict__ Ah, const bf16* __restrict__ Al,
               const bf16* __restrict__ Bh, const bf16* __restrict__ Bl,
               float* __restrict__ Cf, bf16* __restrict__ Oh,
               bf16* __restrict__ Ol, int ldcr, int M, int K, int act)
{
    extern __shared__ char smem[];
    gemm_body<NB>(Ah, Al, Bh, Bl, Cf, Oh, Ol, ldcr, M, K, act,
                  blockIdx.y * 128, blockIdx.x * 64 * NB, smem);
}

// all 6 irreps GEMMs in one launch: blockIdx.z = z*3+l, early-exit on M
__global__ __launch_bounds__(256)
void irr_gemm_k(const bf16* __restrict__ msgh, const bf16* __restrict__ msgl,
                const bf16* __restrict__ wth, const bf16* __restrict__ wtl,
                float* __restrict__ tmp)
{
    extern __shared__ char smem[];
    const int zl = blockIdx.z;
    const int z = zl / 3;
    const int l = zl - z * 3;
    const int ldim[3] = {1, 3, 5};
    const int loff[3] = {L0OFF, L1OFF, L2OFF};
    const int wlo[3] = {WL0_T, WL1_T, WL2_T};
    const int d = ldim[l];
    const int M = NN * d;
    const int bm = blockIdx.y * 128;
    if (bm >= M) return;
    gemm_body<1>(msgh + (size_t)z * ZSZ + loff[l],
                 msgl + (size_t)z * ZSZ + loff[l],
                 wth + wlo[l], wtl + wlo[l],
                 tmp + (size_t)z * ZSZ + loff[l], nullptr, nullptr,
                 CC, M, CC, 0, bm, blockIdx.x * 64, smem);
}

#define SSTG1 (2 * 128 * ROWB + 2 * 64 * ROWB)
#define S_TOT1 (2 * SSTG1)                       // 110592
#define SSTG2 (2 * 128 * ROWB + 2 * 128 * ROWB)
#define S_TOT2 (2 * SSTG2)                       // 147456

// ---------------- fused weight transpose + bf16 split -----------------------
#define TSEG 9
__global__ void transpose_all_k(const float* __restrict__ s0, const float* __restrict__ s1,
                                const float* __restrict__ s2, const float* __restrict__ s3,
                                const float* __restrict__ s4, const float* __restrict__ s5,
                                const float* __restrict__ s6, const float* __restrict__ s7,
                                const float* __restrict__ s8,
                                bf16* __restrict__ wth, bf16* __restrict__ wtl)
{
    const float* srcs[TSEG] = {s0, s1, s2, s3, s4, s5, s6, s7, s8};
    const int Ksrc[TSEG] = {128, 1280, 8, 64, 64, 64, 128, 128, 128};
    const int Kdst[TSEG] = {128, 1280, 64, 64, 64, 64, 128, 128, 128};
    const int Ns[TSEG]   = {128, 128, 64, 64, 64, 384, 128, 128, 128};
    const int bases[TSEG] = {WUP_T, WSK_T, W1_T, W2_T, W3_T, W4_T,
                             WL0_T, WL1_T, WL2_T};
    for (int i = blockIdx.x * blockDim.x + threadIdx.x; i < WT_TOTAL;
         i += gridDim.x * blockDim.x) {
        int seg = 0;
#pragma unroll
        for (int s = 1; s < TSEG; s++)
            if (i >= bases[s]) seg = s;
        int local = i - bases[seg];
        int K = Kdst[seg];
        int c = local / K;
        int k = local - c * K;
        float v;
        if (seg == 1) {
            // k = vA*128 + u ; src W_skip[u][vA][c] = s1[u*1280 + vA*128 + c]
            int vA = k >> 7;
            int u = k & 127;
            v = __ldg(&s1[(size_t)u * 1280 + vA * 128 + c]);
        } else {
            v = (k < Ksrc[seg]) ? __ldg(&srcs[seg][(size_t)k * Ns[seg] + c]) : 0.f;
        }
        bf16 hi, lo;
        split1(v, hi, lo);
        wth[i] = hi;
        wtl[i] = lo;
    }
}

// ---------------- fp32 -> bf16 hi/lo convert (with K padding) ---------------
__global__ void conv_split_k(const float* __restrict__ in, bf16* __restrict__ oh,
                             bf16* __restrict__ ol, int M, int Kin, int Kout)
{
    for (int i = blockIdx.x * blockDim.x + threadIdx.x; i < M * Kout;
         i += gridDim.x * blockDim.x) {
        int r = i / Kout;
        int k = i - r * Kout;
        float v = (k < Kin) ? __ldg(&in[(size_t)r * Kin + k]) : 0.f;
        bf16 hi, lo;
        split1(v, hi, lo);
        oh[i] = hi;
        ol[i] = lo;
    }
}

// permuted variant: row p of output = input row eid[p]
__global__ void conv_split_perm_k(const float* __restrict__ in,
                                  const int* __restrict__ eid,
                                  bf16* __restrict__ oh, bf16* __restrict__ ol,
                                  int M, int Kin, int Kout)
{
    for (int i = blockIdx.x * blockDim.x + threadIdx.x; i < M * Kout;
         i += gridDim.x * blockDim.x) {
        int r = i / Kout;
        int k = i - r * Kout;
        int e = __ldg(&eid[r]);
        float v = (k < Kin) ? __ldg(&in[(size_t)e * Kin + k]) : 0.f;
        bf16 hi, lo;
        split1(v, hi, lo);
        oh[i] = hi;
        ol[i] = lo;
    }
}

// pack sorted edge SH: ys[p][0..8] = yr[eid[p]], ys[p][9..17] = yi[eid[p]]
__global__ void pack_ys_k(const float* __restrict__ yr,
                          const float* __restrict__ yi,
                          const int* __restrict__ eid,
                          float* __restrict__ ys)
{
    for (int i = blockIdx.x * blockDim.x + threadIdx.x; i < EE * 18;
         i += gridDim.x * blockDim.x) {
        int p = i / 18;
        int j = i - p * 18;
        int e = __ldg(&eid[p]);
        float v = (j < 9) ? __ldg(&yr[(size_t)e * 9 + j])
                          : __ldg(&yi[(size_t)e * 9 + j - 9]);
        ys[i] = v;
    }
}

// ---------------- merge: tmp per-l coalesced -> out [n][c*9+jm] -------------
#define MPAD 132
__global__ void merge_k(const float* __restrict__ tmp, float* __restrict__ out)
{
    int n = blockIdx.x;
    int z = blockIdx.y;
    const float* t = tmp + (size_t)z * ZSZ;
    float* o = out + (size_t)z * NN * MID + (size_t)n * MID;
    __shared__ float s[9 * MPAD];
    int c = threadIdx.x;    // 128
    s[0 * MPAD + c] = t[L0OFF + (size_t)n * CC + c];
#pragma unroll
    for (int m = 0; m < 3; m++)
        s[(1 + m) * MPAD + c] = t[L1OFF + ((size_t)n * 3 + m) * CC + c];
#pragma unroll
    for (int m = 0; m < 5; m++)
        s[(4 + m) * MPAD + c] = t[L2OFF + ((size_t)n * 5 + m) * CC + c];
    __syncthreads();
#pragma unroll
    for (int it = 0; it < 9; it++) {
        int i = it * 128 + c;
        int cc = i / 9;
        int jm = i - cc * 9;
        o[i] = s[jm * MPAD + cc];
    }
}

// ---------------- y outer product: y[n, v*128+u], coalesced -----------------
__global__ void yprep_k(const float* __restrict__ feats,
                        const float* __restrict__ attrs,
                        bf16* __restrict__ yh, bf16* __restrict__ yl)
{
    int n = blockIdx.x;
    __shared__ float sf[CC];
    __shared__ float sa[AA];
    if (threadIdx.x < CC) sf[threadIdx.x] = feats[(size_t)n * CC + threadIdx.x];
    if (threadIdx.x < AA) sa[threadIdx.x] = attrs[(size_t)n * AA + threadIdx.x];
    __syncthreads();
#pragma unroll
    for (int i = threadIdx.x; i < CC * AA; i += 256) {
        int v = i >> 7;          // attr index
        int u = i & 127;         // channel
        float val = sf[u] * sa[v];
        bf16 hi, lo;
        split1(val, hi, lo);
        yh[(size_t)n * (CC * AA) + i] = hi;
        yl[(size_t)n * (CC * AA) + i] = lo;
    }
}

// ---------------- CSR build -------------------------------------------------
__global__ void zero_deg_k(int* deg, int n)
{
    int i = blockIdx.x * blockDim.x + threadIdx.x;
    if (i < n) deg[i] = 0;
}
__global__ void count_deg_k(const int* __restrict__ recv, int* deg, int e)
{
    int i = blockIdx.x * blockDim.x + threadIdx.x;
    if (i < e) atomicAdd(&deg[recv[i]], 1);
}
__global__ void scan_k(const int* __restrict__ deg, int* off, int* pos, int n)
{
    __shared__ int wsum[32];
    __shared__ int carry_s;
    const int tid = threadIdx.x;
    const int lane = tid & 31;
    const int w = tid >> 5;
    if (tid == 0) carry_s = 0;
    __syncthreads();
    for (int base = 0; base < n; base += 1024) {
        int i = base + tid;
        int v = (i < n) ? deg[i] : 0;
        int x = v;
#pragma unroll
        for (int st = 1; st < 32; st <<= 1) {
            int t = __shfl_up_sync(0xFFFFFFFF, x, st);
            if (lane >= st) x += t;
        }
        if (lane == 31) wsum[w] = x;
        __syncthreads();
        if (w == 0) {
            int ws = (lane < 32) ? wsum[lane] : 0;
#pragma unroll
            for (int st = 1; st < 32; st <<= 1) {
                int t = __shfl_up_sync(0xFFFFFFFF, ws, st);
                if (lane >= st) ws += t;
            }
            wsum[lane] = ws;
        }
        __syncthreads();
        int incl = x + (w > 0 ? wsum[w - 1] : 0) + carry_s;
        int excl = incl - v;
        if (i < n) { off[i] = excl; pos[i] = excl; }
        __syncthreads();
        if (tid == 1023) carry_s = incl;
        __syncthreads();
    }
    if (threadIdx.x == 0) off[n] = carry_s;
}
__global__ void fill_eid_k(const int* __restrict__ recv,
                           const int* __restrict__ send,
                           int* pos, int* eid, int* sperm, int e)
{
    int i = blockIdx.x * blockDim.x + threadIdx.x;
    if (i < e) {
        int p = atomicAdd(&pos[recv[i]], 1);
        eid[p] = i;
        sperm[p] = send[i];
    }
}

// ---------------- gather: TP + segment sum (receiver-sorted inputs) ---------
__global__ void gather_k(const float* __restrict__ h,
                         const float* __restrict__ tpw,
                         const float* __restrict__ ys,
                         const int* __restrict__ sperm,
                         const int* __restrict__ off,
                         bf16* __restrict__ msgh, bf16* __restrict__ msgl)
{
    int n = blockIdx.x;
    int c = threadIdx.x;   // 128 threads, one per channel
    float ar[9], ai[9];
#pragma unroll
    for (int j = 0; j < 9; j++) { ar[j] = 0.f; ai[j] = 0.f; }

    int e0 = __ldg(&off[n]);
    int e1 = __ldg(&off[n + 1]);
    for (int p = e0; p < e1; p++) {
        int s = __ldg(&sperm[p]);
        float hc = h[(size_t)s * CC + c];      // L2-resident (5 MB)
        const float* tw = tpw + (size_t)p * 384;   // sequential
        float xw0 = hc * tw[c];
        float xw1 = hc * tw[128 + c];
        float xw2 = hc * tw[256 + c];
        const float* er = ys + (size_t)p * 18;     // sequential
        const float* ei = er + 9;
        ar[0] += xw0 * __ldg(&er[0]);
        ai[0] += xw0 * __ldg(&ei[0]);
#pragma unroll
        for (int m = 0; m < 3; m++) {
            ar[1 + m] += xw1 * __ldg(&er[1 + m]);
            ai[1 + m] += xw1 * __ldg(&ei[1 + m]);
        }
#pragma unroll
        for (int m = 0; m < 5; m++) {
            ar[4 + m] += xw2 * __ldg(&er[4 + m]);
            ai[4 + m] += xw2 * __ldg(&ei[4 + m]);
        }
    }

    // per-l contiguous layout, split to bf16 hi/lo
#pragma unroll
    for (int z = 0; z < 2; z++) {
        const float* a = z ? ai : ar;
        bf16* mh = msgh + (size_t)z * ZSZ;
        bf16* ml = msgl + (size_t)z * ZSZ;
        bf16 hi, lo;
        split1(a[0], hi, lo);
        mh[L0OFF + (size_t)n * CC + c] = hi;
        ml[L0OFF + (size_t)n * CC + c] = lo;
#pragma unroll
        for (int m = 0; m < 3; m++) {
            split1(a[1 + m], hi, lo);
            mh[L1OFF + ((size_t)n * 3 + m) * CC + c] = hi;
            ml[L1OFF + ((size_t)n * 3 + m) * CC + c] = lo;
        }
#pragma unroll
        for (int m = 0; m < 5; m++) {
            split1(a[4 + m], hi, lo);
            mh[L2OFF + ((size_t)n * 5 + m) * CC + c] = hi;
            ml[L2OFF + ((size_t)n * 5 + m) * CC + c] = lo;
        }
    }
}

// ---------------- launch ----------------------------------------------------
static inline float* symf(const void* sym)
{
    void* p = nullptr;
    cudaGetSymbolAddress(&p, sym);
    return (float*)p;
}
static inline bf16* symb(const void* sym)
{
    void* p = nullptr;
    cudaGetSymbolAddress(&p, sym);
    return (bf16*)p;
}
static inline int* symi(const void* sym)
{
    void* p = nullptr;
    cudaGetSymbolAddress(&p, sym);
    return (int*)p;
}

static inline void tc_gemm(const bf16* Ah, const bf16* Al,
                           const bf16* Bh, const bf16* Bl,
                           float* Cf, bf16* Oh, bf16* Ol, int ldcr,
                           int M, int Ncols, int K, int act, int nb)
{
    if (nb == 2) {
        dim3 grid(Ncols / 128, (M + 127) / 128);
        tc_gemm_k<2><<<grid, 256, S_TOT2>>>(Ah, Al, Bh, Bl, Cf, Oh, Ol, ldcr,
                                            M, K, act);
    } else {
        dim3 grid(Ncols / 64, (M + 127) / 128);
        tc_gemm_k<1><<<grid, 256, S_TOT1>>>(Ah, Al, Bh, Bl, Cf, Oh, Ol, ldcr,
                                            M, K, act);
    }
}

extern "C" void kernel_launch(void* const* d_in, const int* in_sizes, int n_in,
                              void* d_out, int out_size)
{
    const float* node_attrs = (const float*)d_in[0];
    const float* node_feats = (const float*)d_in[1];
    const float* yr         = (const float*)d_in[2];
    const float* yi         = (const float*)d_in[3];
    const float* edge_feats = (const float*)d_in[4];
    const int*   edge_index = (const int*)d_in[5];
    const float* W_up   = (const float*)d_in[6];
    const float* W_skip = (const float*)d_in[7];
    const float* W1     = (const float*)d_in[8];
    const float* W2     = (const float*)d_in[9];
    const float* W3     = (const float*)d_in[10];
    const float* W4     = (const float*)d_in[11];
    const float* Wl[3]  = { (const float*)d_in[12], (const float*)d_in[13],
                            (const float*)d_in[14] };
    float* out = (float*)d_out;

    static int smem_set = 0;
    if (!smem_set) {
        cudaFuncSetAttribute(tc_gemm_k<1>,
                             cudaFuncAttributeMaxDynamicSharedMemorySize, S_TOT1);
        cudaFuncSetAttribute(tc_gemm_k<2>,
                             cudaFuncAttributeMaxDynamicSharedMemorySize, S_TOT2);
        cudaFuncSetAttribute(irr_gemm_k,
                             cudaFuncAttributeMaxDynamicSharedMemorySize, S_TOT1);
        smem_set = 1;
    }

    float* hh   = symf(g_h);
    float* tpw  = symf(g_tpw);
    float* ys   = symf(g_ys);
    float* tmp  = symf(g_tmp);
    bf16* nfh = symb(g_nfh); bf16* nfl = symb(g_nfl);
    bf16* efh = symb(g_efh); bf16* efl = symb(g_efl);
    bf16* yh  = symb(g_yh);  bf16* yl  = symb(g_yl);
    bf16* tah = symb(g_tah); bf16* tal = symb(g_tal);
    bf16* tbh = symb(g_tbh); bf16* tbl = symb(g_tbl);
    bf16* msgh = symb(g_msgh); bf16* msgl = symb(g_msgl);
    bf16* wth = symb(g_wth); bf16* wtl = symb(g_wtl);
    int* deg = symi(g_deg);
    int* off = symi(g_off);
    int* pos = symi(g_pos);
    int* eid = symi(g_eid);
    int* sperm = symi(g_sperm);

    const int* recv = edge_index + EE;
    const int* send = edge_index;

    // launch order: profiler's 4th launch = sc GEMM (NB=1, grid 158)
    yprep_k<<<NN, 256>>>(node_feats, node_attrs, yh, yl);                 // 1
    transpose_all_k<<<1040, 256>>>(W_up, W_skip, W1, W2, W3, W4,
                                   Wl[0], Wl[1], Wl[2], wth, wtl);        // 2
    conv_split_k<<<1024, 256>>>(node_feats, nfh, nfl, NN, CC, CC);        // 3
    // sc = y @ W_skip
    tc_gemm(yh, yl, wth + WSK_T, wtl + WSK_T, out + SC_OFF, nullptr, nullptr,
            CC, NN, CC, CC * AA, 0, 1);                                   // 4
    // CSR (needed before permuted edge pipeline)
    zero_deg_k<<<(NN + 255) / 256, 256>>>(deg, NN);
    count_deg_k<<<(EE + 255) / 256, 256>>>(recv, deg, EE);
    scan_k<<<1, 1024>>>(deg, off, pos, NN);
    fill_eid_k<<<(EE + 255) / 256, 256>>>(recv, send, pos, eid, sperm, EE);
    // permuted edge-feature split + SH pack
    conv_split_perm_k<<<2048, 256>>>(edge_feats, eid, efh, efl, EE, FF, 64);
    pack_ys_k<<<2048, 256>>>(yr, yi, eid, ys);
    // h = node_feats @ W_up
    tc_gemm(nfh, nfl, wth + WUP_T, wtl + WUP_T, hh, nullptr, nullptr, CC,
            NN, CC, CC, 0, 1);
    // edge MLP (bf16 hi/lo chain, receiver-sorted rows)
    tc_gemm(efh, efl, wth + W1_T, wtl + W1_T, nullptr, tah, tal, 64,
            EE, 64, 64, 1, 1);
    tc_gemm(tah, tal, wth + W2_T, wtl + W2_T, nullptr, tbh, tbl, 64,
            EE, 64, 64, 1, 1);
    tc_gemm(tbh, tbl, wth + W3_T, wtl + W3_T, nullptr, tah, tal, 64,
            EE, 64, 64, 1, 1);
    tc_gemm(tah, tal, wth + W4_T, wtl + W4_T, tpw, nullptr, nullptr, 384,
            EE, 384, 64, 0, 2);
    // tensor product + segment sum (streaming tpw/ys; h via L2)
    gather_k<<<NN, 128>>>(hh, tpw, ys, sperm, off, msgh, msgl);
    // all 6 irreps GEMMs in one launch
    irr_gemm_k<<<dim3(2, 391, 6), 256, S_TOT1>>>(msgh, msgl, wth, wtl, tmp);
    // merge tmp -> out (coalesced both sides)
    merge_k<<<dim3(NN, 2), 128>>>(tmp, out);
}

// round 15
// speedup vs baseline: 1.4642x; 1.3397x over previous
#include <cuda_runtime.h>
#include <cuda_bf16.h>
#include <math.h>
#include <stdint.h>

// Problem constants (fixed shapes)
#define NN 10000
#define EE 128000
#define CC 128
#define AA 10
#define FF 8
#define MID 1152                       // C * 9
#define SC_OFF (2 * NN * MID)

// msg internal layout per z: [ l0: N*1*C | l1: N*3*C | l2: N*5*C ]
#define ZSZ   (NN * 9 * CC)
#define L0OFF 0
#define L1OFF (NN * CC)
#define L2OFF (4 * NN * CC)

typedef __nv_bfloat16 bf16;

// ---------------- scratch (static device globals) ---------------------------
__device__ __align__(128) float g_h[NN * CC];              // fp32 (gather input)
__device__ __align__(128) float g_tpw[(size_t)EE * 384];   // fp32, receiver-sorted
__device__ __align__(128) float g_ys[(size_t)EE * 18];     // sorted edge SH (r|i)
__device__ __align__(128) float g_tmp[2 * ZSZ];            // irreps GEMM output
// bf16 hi/lo operand pairs
__device__ __align__(128) bf16 g_nfh[NN * CC];
__device__ __align__(128) bf16 g_nfl[NN * CC];
__device__ __align__(128) bf16 g_yh[NN * CC * AA];
__device__ __align__(128) bf16 g_yl[NN * CC * AA];
__device__ __align__(128) bf16 g_msgh[2 * ZSZ];
__device__ __align__(128) bf16 g_msgl[2 * ZSZ];
__device__ __align__(128) bf16 g_wth[266240];
__device__ __align__(128) bf16 g_wtl[266240];
__device__ int   g_deg[NN + 8];
__device__ int   g_off[NN + 8];
__device__ int   g_pos[NN + 8];
__device__ int   g_eid[EE];
__device__ int   g_sperm[EE];

// transposed-weight offsets inside g_wt (all K padded to multiples of 64)
#define WUP_T 0
#define WSK_T 16384
#define W1_T  180224
#define W2_T  184320
#define W3_T  188416
#define W4_T  192512
#define WL0_T 217088
#define WL1_T 233472
#define WL2_T 249856
#define WT_TOTAL 266240

// ---------------- helpers ---------------------------------------------------
__device__ __forceinline__ uint32_t smem_to_u32(const void* p) {
    uint32_t a;
    asm("{ .reg .u64 t; cvta.to.shared.u64 t, %1; cvt.u32.u64 %0, t; }"
        : "=r"(a) : "l"(p));
    return a;
}

__device__ __forceinline__ void ldm_x4(uint32_t addr, uint32_t* r) {
    asm volatile("ldmatrix.sync.aligned.m8n8.x4.shared.b16 {%0,%1,%2,%3}, [%4];"
                 : "=r"(r[0]), "=r"(r[1]), "=r"(r[2]), "=r"(r[3]) : "r"(addr));
}

__device__ __forceinline__ void mma16816(float* d, const uint32_t* a,
                                         const uint32_t* b) {
    asm volatile("mma.sync.aligned.m16n8k16.row.col.f32.bf16.bf16.f32 "
                 "{%0,%1,%2,%3}, {%4,%5,%6,%7}, {%8,%9}, {%0,%1,%2,%3};"
                 : "+f"(d[0]), "+f"(d[1]), "+f"(d[2]), "+f"(d[3])
                 : "r"(a[0]), "r"(a[1]), "r"(a[2]), "r"(a[3]),
                   "r"(b[0]), "r"(b[1]));
}

#define CP16(dst, src) \
    asm volatile("cp.async.cg.shared.global [%0], [%1], 16;" \
                 :: "r"(dst), "l"(src) : "memory")
#define CP_COMMIT() asm volatile("cp.async.commit_group;" ::: "memory")
#define CP_WAIT0()  asm volatile("cp.async.wait_group 0;" ::: "memory")
#define CP_WAIT1()  asm volatile("cp.async.wait_group 1;" ::: "memory")

__device__ __forceinline__ void split1(float v, bf16& hi, bf16& lo)
{
    hi = __float2bfloat16_rn(v);
    lo = __float2bfloat16_rn(v - __bfloat162float(hi));
}
__device__ __forceinline__ uint32_t packbf(float a, float b)
{
    __nv_bfloat162 t = __floats2bfloat162_rn(a, b);
    return *reinterpret_cast<uint32_t*>(&t);
}
__device__ __forceinline__ uint32_t packlo(float a, float b, uint32_t hi)
{
    __nv_bfloat162 h = *reinterpret_cast<__nv_bfloat162*>(&hi);
    float2 f = __bfloat1622float2(h);
    return packbf(a - f.x, b - f.y);
}

// ---------------- mma.sync bf16 pre-split GEMM body -------------------------
// C = act( A[MxK] @ Bt[Ncols x K]^T ).  A,B given as bf16 hi/lo pairs.
// Block tile 128 x (64*NB), K-chunk 64, 8 warps (4m x 2n), warp tile 32 x 32*NB.
#define ROWB 144

template<int NB>
__device__ __forceinline__
void gemm_body(const bf16* __restrict__ Ah, const bf16* __restrict__ Al,
               const bf16* __restrict__ Bh, const bf16* __restrict__ Bl,
               float* __restrict__ Cf, bf16* __restrict__ Oh,
               bf16* __restrict__ Ol, int ldcr, int lda, int ldb,
               int M, int K, int act, int atomic, int bm, int bn, char* smem)
{
    constexpr int BN = 64 * NB;
    constexpr int SA_H = 0;
    constexpr int SA_L = 128 * ROWB;
    constexpr int SB_H = 2 * 128 * ROWB;
    constexpr int SB_L = 2 * 128 * ROWB + BN * ROWB;
    constexpr int SSTG = 2 * 128 * ROWB + 2 * BN * ROWB;
    constexpr int BSH = (NB == 1) ? 9 : 10;   // log2(BN*8)

    const uint32_t sb = smem_to_u32(smem);
    const int tid = threadIdx.x;
    const int lane = tid & 31;
    const int wid = tid >> 5;
    const int wm = (wid & 3) * 32;
    const int wn = (wid >> 2) * 32 * NB;
    const int nchunks = K >> 6;

    float acc[2][4 * NB][4];
#pragma unroll
    for (int i = 0; i < 2; i++)
#pragma unroll
        for (int j = 0; j < 4 * NB; j++)
#pragma unroll
            for (int q = 0; q < 4; q++) acc[i][j][q] = 0.f;

    auto stage = [&](int ch) {
        const int k0 = ch << 6;
        const uint32_t stg = sb + (uint32_t)((ch & 1) * SSTG);
#pragma unroll
        for (int li = 0; li < 8; li++) {
            int u = tid + li * 256;
            int buf = u >> 10;
            int idx = u & 1023;
            int r = idx >> 3;
            int c = idx & 7;
            int gr = bm + r;
            if (gr >= M) gr = M - 1;      // clamp: garbage rows are discarded
            const bf16* src = (buf ? Al : Ah) + (size_t)gr * lda + k0 + c * 8;
            uint32_t dst = stg + (buf ? SA_L : SA_H) + r * ROWB + c * 16;
            CP16(dst, src);
        }
#pragma unroll
        for (int li = 0; li < 4 * NB; li++) {
            int u = tid + li * 256;
            int buf = u >> BSH;
            int idx = u & ((1 << BSH) - 1);
            int r = idx >> 3;
            int c = idx & 7;
            const bf16* src = (buf ? Bl : Bh) + (size_t)(bn + r) * ldb + k0 + c * 8;
            uint32_t dst = stg + (buf ? SB_L : SB_H) + r * ROWB + c * 16;
            CP16(dst, src);
        }
        CP_COMMIT();
    };

    const uint32_t aRow = wm + (lane & 15);
    const uint32_t aKp = (lane >> 4) * 8;
    const uint32_t aOff0 = aRow * ROWB + aKp * 2;
    const uint32_t aOff1 = (aRow + 16) * ROWB + aKp * 2;
    const uint32_t bRow = (lane & 7) + ((lane >> 4) * 8);
    const uint32_t bKp = ((lane >> 3) & 1) * 8;
    uint32_t bOffs[2 * NB];
#pragma unroll
    for (int g = 0; g < 2 * NB; g++)
        bOffs[g] = (wn + g * 16 + bRow) * ROWB + bKp * 2;

    stage(0);

    for (int ch = 0; ch < nchunks; ch++) {
        if (ch + 1 < nchunks) {
            stage(ch + 1);
            CP_WAIT1();
        } else {
            CP_WAIT0();
        }
        __syncthreads();
        const uint32_t stg = sb + (uint32_t)((ch & 1) * SSTG);

#pragma unroll
        for (int ks = 0; ks < 4; ks++) {
            const uint32_t k2 = (uint32_t)(ks * 32);
            uint32_t ah0[4], ah1[4], al0[4], al1[4];
            uint32_t bb[2 * NB][4];
            ldm_x4(stg + SA_H + aOff0 + k2, ah0);
            ldm_x4(stg + SA_H + aOff1 + k2, ah1);
#pragma unroll
            for (int g = 0; g < 2 * NB; g++)
                ldm_x4(stg + SB_H + bOffs[g] + k2, bb[g]);
#pragma unroll
            for (int g = 0; g < 2 * NB; g++)
#pragma unroll
                for (int h2 = 0; h2 < 2; h2++) {
                    mma16816(acc[0][g * 2 + h2], ah0, bb[g] + 2 * h2);
                    mma16816(acc[1][g * 2 + h2], ah1, bb[g] + 2 * h2);
                }
            ldm_x4(stg + SA_L + aOff0 + k2, al0);
            ldm_x4(stg + SA_L + aOff1 + k2, al1);
#pragma unroll
            for (int g = 0; g < 2 * NB; g++)
#pragma unroll
                for (int h2 = 0; h2 < 2; h2++) {
                    mma16816(acc[0][g * 2 + h2], al0, bb[g] + 2 * h2);
                    mma16816(acc[1][g * 2 + h2], al1, bb[g] + 2 * h2);
                }
#pragma unroll
            for (int g = 0; g < 2 * NB; g++)
                ldm_x4(stg + SB_L + bOffs[g] + k2, bb[g]);
#pragma unroll
            for (int g = 0; g < 2 * NB; g++)
#pragma unroll
                for (int h2 = 0; h2 < 2; h2++) {
                    mma16816(acc[0][g * 2 + h2], ah0, bb[g] + 2 * h2);
                    mma16816(acc[1][g * 2 + h2], ah1, bb[g] + 2 * h2);
                }
        }
        __syncthreads();
    }

    // ---- epilogue ----
#pragma unroll
    for (int mt = 0; mt < 2; mt++) {
        int r0g = bm + wm + mt * 16 + (lane >> 2);
#pragma unroll
        for (int nt = 0; nt < 4 * NB; nt++) {
            int cg = bn + wn + nt * 8 + (lane & 3) * 2;
            float* d = acc[mt][nt];
#pragma unroll
            for (int half = 0; half < 2; half++) {
                int r = r0g + half * 8;
                if (r >= M) continue;
                float v0 = d[half * 2 + 0];
                float v1 = d[half * 2 + 1];
                if (act) {
                    v0 = v0 / (1.f + __expf(-v0));
                    v1 = v1 / (1.f + __expf(-v1));
                }
                size_t base = (size_t)r * ldcr + cg;
                if (Cf) {
                    if (atomic) {
                        atomicAdd(Cf + base, v0);
                        atomicAdd(Cf + base + 1, v1);
                    } else {
                        Cf[base] = v0;
                        Cf[base + 1] = v1;
                    }
                }
                if (Oh) {
                    bf16 h0, l0, h1, l1;
                    split1(v0, h0, l0);
                    split1(v1, h1, l1);
                    Oh[base] = h0;
                    Ol[base] = l0;
                    Oh[base + 1] = h1;
                    Ol[base + 1] = l1;
                }
            }
        }
    }
}

template<int NB>
__global__ __launch_bounds__(256)
void tc_gemm_k(const bf16* __restrict__ Ah, const bf16* __restrict__ Al,
               const bf16* __restrict__ Bh, const bf16* __restrict__ Bl,
               float* __restrict__ Cf, bf16* __restrict__ Oh,
               bf16* __restrict__ Ol, int ldcr, int lda, int ldb,
               int M, int K, int act, int atomic)
{
    extern __shared__ char smem[];
    int koff = blockIdx.z * K;    // split-K slice offset
    gemm_body<NB>(Ah + koff, Al + koff, Bh + koff, Bl + koff,
                  Cf, Oh, Ol, ldcr, lda, ldb, M, K, act, atomic,
                  blockIdx.y * 128, blockIdx.x * 64 * NB, smem);
}

// all 6 irreps GEMMs in one launch: blockIdx.z = z*3+l, early-exit on M
__global__ __launch_bounds__(256)
void irr_gemm_k(const bf16* __restrict__ msgh, const bf16* __restrict__ msgl,
                const bf16* __restrict__ wth, const bf16* __restrict__ wtl,
                float* __restrict__ tmp)
{
    extern __shared__ char smem[];
    const int zl = blockIdx.z;
    const int z = zl / 3;
    const int l = zl - z * 3;
    const int ldim[3] = {1, 3, 5};
    const int loff[3] = {L0OFF, L1OFF, L2OFF};
    const int wlo[3] = {WL0_T, WL1_T, WL2_T};
    const int d = ldim[l];
    const int M = NN * d;
    const int bm = blockIdx.y * 128;
    if (bm >= M) return;
    gemm_body<1>(msgh + (size_t)z * ZSZ + loff[l],
                 msgl + (size_t)z * ZSZ + loff[l],
                 wth + wlo[l], wtl + wlo[l],
                 tmp + (size_t)z * ZSZ + loff[l], nullptr, nullptr,
                 CC, CC, CC, M, CC, 0, 0, bm, blockIdx.x * 64, smem);
}

#define SSTG1 (2 * 128 * ROWB + 2 * 64 * ROWB)
#define S_TOT1 (2 * SSTG1)                       // 110592

// ---------------- fused edge MLP: ef -> L1 -> L2 -> L3 -> W4 -> tpw ---------
// 256 threads = 8 warps x 32 rows = 256 edges per block; grid = EE/256 = 500.
// Activations stay in registers via C-frag -> A-frag repacking.
// Weights preloaded in smem, ldmatrix-ready 144B rows, hi block then lo block.
#define MW1 0
#define MW2 9216
#define MW3 18432
#define MW4 27648
#define MLO 82944            // lo region offset
#define S_MLP (2 * 82944)    // 165888

__device__ __forceinline__ void silu_acc(float acc[2][8][4])
{
#pragma unroll
    for (int mt = 0; mt < 2; mt++)
#pragma unroll
        for (int u = 0; u < 8; u++)
#pragma unroll
            for (int q = 0; q < 4; q++) {
                float v = acc[mt][u][q];
                acc[mt][u][q] = v / (1.f + __expf(-v));
            }
}

__device__ __forceinline__ void repack(const float acc[2][8][4],
                                       uint32_t aH[2][4][4],
                                       uint32_t aL[2][4][4])
{
#pragma unroll
    for (int mt = 0; mt < 2; mt++)
#pragma unroll
        for (int t = 0; t < 4; t++) {
            const float* c0 = acc[mt][2 * t];
            const float* c1 = acc[mt][2 * t + 1];
            aH[mt][t][0] = packbf(c0[0], c0[1]);
            aH[mt][t][1] = packbf(c0[2], c0[3]);
            aH[mt][t][2] = packbf(c1[0], c1[1]);
            aH[mt][t][3] = packbf(c1[2], c1[3]);
            aL[mt][t][0] = packlo(c0[0], c0[1], aH[mt][t][0]);
            aL[mt][t][1] = packlo(c0[2], c0[3], aH[mt][t][1]);
            aL[mt][t][2] = packlo(c1[0], c1[1], aH[mt][t][2]);
            aL[mt][t][3] = packlo(c1[2], c1[3], aH[mt][t][3]);
        }
}

template<int NK>
__device__ __forceinline__ void mma_layer(uint32_t sb, int whoff,
                                          const uint32_t aH[2][4][4],
                                          const uint32_t aL[2][4][4],
                                          float acc[2][8][4],
                                          uint32_t bRowPix)
{
#pragma unroll
    for (int mt = 0; mt < 2; mt++)
#pragma unroll
        for (int u = 0; u < 8; u++)
#pragma unroll
            for (int q = 0; q < 4; q++) acc[mt][u][q] = 0.f;
#pragma unroll
    for (int ks = 0; ks < NK; ks++) {
#pragma unroll
        for (int g = 0; g < 4; g++) {
            uint32_t base = sb + whoff + (uint32_t)(g * 16) * ROWB + bRowPix
                            + (uint32_t)(ks * 32);
            uint32_t bb[4];
            ldm_x4(base, bb);
#pragma unroll
            for (int mt = 0; mt < 2; mt++) {
                mma16816(acc[mt][2 * g], aH[mt][ks], bb + 0);
                mma16816(acc[mt][2 * g + 1], aH[mt][ks], bb + 2);
                mma16816(acc[mt][2 * g], aL[mt][ks], bb + 0);
                mma16816(acc[mt][2 * g + 1], aL[mt][ks], bb + 2);
            }
            ldm_x4(base + MLO, bb);
#pragma unroll
            for (int mt = 0; mt < 2; mt++) {
                mma16816(acc[mt][2 * g], aH[mt][ks], bb + 0);
                mma16816(acc[mt][2 * g + 1], aH[mt][ks], bb + 2);
            }
        }
    }
}

__global__ __launch_bounds__(256)
void mlp_fused_k(const float* __restrict__ edge_feats,
                 const int* __restrict__ eid,
                 const bf16* __restrict__ wth, const bf16* __restrict__ wtl,
                 float* __restrict__ tpw)
{
    extern __shared__ char smem[];
    const uint32_t sb = smem_to_u32(smem);
    const int tid = threadIdx.x;
    const int lane = tid & 31;
    const int w = tid >> 5;
    const int bm = blockIdx.x * 256;

    // ---- load weights (hi & lo) into smem ----
    for (int u = tid; u < 4608; u += 256) {
        int row = u >> 3;
        int ch = u & 7;
        int srcoff, dsth;
        if (row < 64)       { srcoff = W1_T + row * 64;        dsth = MW1 + row * ROWB; }
        else if (row < 128) { srcoff = W2_T + (row - 64) * 64;  dsth = MW2 + (row - 64) * ROWB; }
        else if (row < 192) { srcoff = W3_T + (row - 128) * 64; dsth = MW3 + (row - 128) * ROWB; }
        else                { srcoff = W4_T + (row - 192) * 64; dsth = MW4 + (row - 192) * ROWB; }
        CP16(sb + dsth + ch * 16, wth + srcoff + ch * 8);
        CP16(sb + dsth + MLO + ch * 16, wtl + srcoff + ch * 8);
    }
    CP_COMMIT();

    // ---- load ef (K=8) directly into L1 A-fragments ----
    uint32_t aH[2][4][4], aL[2][4][4];
    const int rbase = bm + w * 32 + (lane >> 2);
    const int kc = (lane & 3) * 2;
#pragma unroll
    for (int mt = 0; mt < 2; mt++) {
        int r0 = rbase + mt * 16;
        int e0 = __ldg(&eid[r0]);
        int e1 = __ldg(&eid[r0 + 8]);
        float2 v0 = *(const float2*)(edge_feats + (size_t)e0 * FF + kc);
        float2 v1 = *(const float2*)(edge_feats + (size_t)e1 * FF + kc);
        aH[mt][0][0] = packbf(v0.x, v0.y);
        aH[mt][0][1] = packbf(v1.x, v1.y);
        aH[mt][0][2] = 0;
        aH[mt][0][3] = 0;
        aL[mt][0][0] = packlo(v0.x, v0.y, aH[mt][0][0]);
        aL[mt][0][1] = packlo(v1.x, v1.y, aH[mt][0][1]);
        aL[mt][0][2] = 0;
        aL[mt][0][3] = 0;
    }

    CP_WAIT0();
    __syncthreads();

    const uint32_t bRowPix = ((lane & 7) + ((lane >> 4) * 8)) * ROWB
                             + (((lane >> 3) & 1) * 8) * 2;

    float acc[2][8][4];
    // L1 (K=16, zeros beyond k=8)
    mma_layer<1>(sb, MW1, aH, aL, acc, bRowPix);
    silu_acc(acc);
    repack(acc, aH, aL);
    // L2
    mma_layer<4>(sb, MW2, aH, aL, acc, bRowPix);
    silu_acc(acc);
    repack(acc, aH, aL);
    // L3
    mma_layer<4>(sb, MW3, aH, aL, acc, bRowPix);
    silu_acc(acc);
    repack(acc, aH, aL);
    // W4: 6 groups of 64 cols -> tpw
#pragma unroll 1
    for (int grp = 0; grp < 6; grp++) {
        mma_layer<4>(sb, MW4 + grp * 64 * ROWB, aH, aL, acc, bRowPix);
#pragma unroll
        for (int mt = 0; mt < 2; mt++) {
            int r = rbase + mt * 16;
#pragma unroll
            for (int u = 0; u < 8; u++) {
                int col = grp * 64 + u * 8 + kc;
                float2 v01 = make_float2(acc[mt][u][0], acc[mt][u][1]);
                float2 v23 = make_float2(acc[mt][u][2], acc[mt][u][3]);
                *(float2*)(tpw + (size_t)r * 384 + col) = v01;
                *(float2*)(tpw + (size_t)(r + 8) * 384 + col) = v23;
            }
        }
    }
}

// ---------------- fused weight transpose + bf16 split -----------------------
#define TSEG 9
__global__ void transpose_all_k(const float* __restrict__ s0, const float* __restrict__ s1,
                                const float* __restrict__ s2, const float* __restrict__ s3,
                                const float* __restrict__ s4, const float* __restrict__ s5,
                                const float* __restrict__ s6, const float* __restrict__ s7,
                                const float* __restrict__ s8,
                                bf16* __restrict__ wth, bf16* __restrict__ wtl)
{
    const float* srcs[TSEG] = {s0, s1, s2, s3, s4, s5, s6, s7, s8};
    const int Ksrc[TSEG] = {128, 1280, 8, 64, 64, 64, 128, 128, 128};
    const int Kdst[TSEG] = {128, 1280, 64, 64, 64, 64, 128, 128, 128};
    const int Ns[TSEG]   = {128, 128, 64, 64, 64, 384, 128, 128, 128};
    const int bases[TSEG] = {WUP_T, WSK_T, W1_T, W2_T, W3_T, W4_T,
                             WL0_T, WL1_T, WL2_T};
    for (int i = blockIdx.x * blockDim.x + threadIdx.x; i < WT_TOTAL;
         i += gridDim.x * blockDim.x) {
        int seg = 0;
#pragma unroll
        for (int s = 1; s < TSEG; s++)
            if (i >= bases[s]) seg = s;
        int local = i - bases[seg];
        int K = Kdst[seg];
        int c = local / K;
        int k = local - c * K;
        float v;
        if (seg == 1) {
            // k = vA*128 + u ; src W_skip[u][vA][c] = s1[u*1280 + vA*128 + c]
            int vA = k >> 7;
            int u = k & 127;
            v = __ldg(&s1[(size_t)u * 1280 + vA * 128 + c]);
        } else {
            v = (k < Ksrc[seg]) ? __ldg(&srcs[seg][(size_t)k * Ns[seg] + c]) : 0.f;
        }
        bf16 hi, lo;
        split1(v, hi, lo);
        wth[i] = hi;
        wtl[i] = lo;
    }
}

// ---------------- fp32 -> bf16 hi/lo convert ---------------------------------
__global__ void conv_split_k(const float* __restrict__ in, bf16* __restrict__ oh,
                             bf16* __restrict__ ol, int M, int Kin, int Kout)
{
    for (int i = blockIdx.x * blockDim.x + threadIdx.x; i < M * Kout;
         i += gridDim.x * blockDim.x) {
        int r = i / Kout;
        int k = i - r * Kout;
        float v = (k < Kin) ? __ldg(&in[(size_t)r * Kin + k]) : 0.f;
        bf16 hi, lo;
        split1(v, hi, lo);
        oh[i] = hi;
        ol[i] = lo;
    }
}

__global__ void zero_f_k(float* __restrict__ p, int n)
{
    int i = blockIdx.x * blockDim.x + threadIdx.x;
    if (i < n) p[i] = 0.f;
}

// pack sorted edge SH: ys[p][0..8] = yr[eid[p]], ys[p][9..17] = yi[eid[p]]
__global__ void pack_ys_k(const float* __restrict__ yr,
                          const float* __restrict__ yi,
                          const int* __restrict__ eid,
                          float* __restrict__ ys)
{
    for (int i = blockIdx.x * blockDim.x + threadIdx.x; i < EE * 18;
         i += gridDim.x * blockDim.x) {
        int p = i / 18;
        int j = i - p * 18;
        int e = __ldg(&eid[p]);
        float v = (j < 9) ? __ldg(&yr[(size_t)e * 9 + j])
                          : __ldg(&yi[(size_t)e * 9 + j - 9]);
        ys[i] = v;
    }
}

// ---------------- merge: tmp per-l coalesced -> out [n][c*9+jm] -------------
#define MPAD 132
__global__ void merge_k(const float* __restrict__ tmp, float* __restrict__ out)
{
    int n = blockIdx.x;
    int z = blockIdx.y;
    const float* t = tmp + (size_t)z * ZSZ;
    float* o = out + (size_t)z * NN * MID + (size_t)n * MID;
    __shared__ float s[9 * MPAD];
    int c = threadIdx.x;    // 128
    s[0 * MPAD + c] = t[L0OFF + (size_t)n * CC + c];
#pragma unroll
    for (int m = 0; m < 3; m++)
        s[(1 + m) * MPAD + c] = t[L1OFF + ((size_t)n * 3 + m) * CC + c];
#pragma unroll
    for (int m = 0; m < 5; m++)
        s[(4 + m) * MPAD + c] = t[L2OFF + ((size_t)n * 5 + m) * CC + c];
    __syncthreads();
#pragma unroll
    for (int it = 0; it < 9; it++) {
        int i = it * 128 + c;
        int cc = i / 9;
        int jm = i - cc * 9;
        o[i] = s[jm * MPAD + cc];
    }
}

// ---------------- y outer product: y[n, v*128+u], coalesced -----------------
__global__ void yprep_k(const float* __restrict__ feats,
                        const float* __restrict__ attrs,
                        bf16* __restrict__ yh, bf16* __restrict__ yl)
{
    int n = blockIdx.x;
    __shared__ float sf[CC];
    __shared__ float sa[AA];
    if (threadIdx.x < CC) sf[threadIdx.x] = feats[(size_t)n * CC + threadIdx.x];
    if (threadIdx.x < AA) sa[threadIdx.x] = attrs[(size_t)n * AA + threadIdx.x];
    __syncthreads();
#pragma unroll
    for (int i = threadIdx.x; i < CC * AA; i += 256) {
        int v = i >> 7;          // attr index
        int u = i & 127;         // channel
        float val = sf[u] * sa[v];
        bf16 hi, lo;
        split1(val, hi, lo);
        yh[(size_t)n * (CC * AA) + i] = hi;
        yl[(size_t)n * (CC * AA) + i] = lo;
    }
}

// ---------------- CSR build -------------------------------------------------
__global__ void zero_deg_k(int* deg, int n)
{
    int i = blockIdx.x * blockDim.x + threadIdx.x;
    if (i < n) deg[i] = 0;
}
__global__ void count_deg_k(const int* __restrict__ recv, int* deg, int e)
{
    int i = blockIdx.x * blockDim.x + threadIdx.x;
    if (i < e) atomicAdd(&deg[recv[i]], 1);
}
__global__ void scan_k(const int* __restrict__ deg, int* off, int* pos, int n)
{
    __shared__ int wsum[32];
    __shared__ int carry_s;
    const int tid = threadIdx.x;
    const int lane = tid & 31;
    const int w = tid >> 5;
    if (tid == 0) carry_s = 0;
    __syncthreads();
    for (int base = 0; base < n; base += 1024) {
        int i = base + tid;
        int v = (i < n) ? deg[i] : 0;
        int x = v;
#pragma unroll
        for (int st = 1; st < 32; st <<= 1) {
            int t = __shfl_up_sync(0xFFFFFFFF, x, st);
            if (lane >= st) x += t;
        }
        if (lane == 31) wsum[w] = x;
        __syncthreads();
        if (w == 0) {
            int ws = (lane < 32) ? wsum[lane] : 0;
#pragma unroll
            for (int st = 1; st < 32; st <<= 1) {
                int t = __shfl_up_sync(0xFFFFFFFF, ws, st);
                if (lane >= st) ws += t;
            }
            wsum[lane] = ws;
        }
        __syncthreads();
        int incl = x + (w > 0 ? wsum[w - 1] : 0) + carry_s;
        int excl = incl - v;
        if (i < n) { off[i] = excl; pos[i] = excl; }
        __syncthreads();
        if (tid == 1023) carry_s = incl;
        __syncthreads();
    }
    if (threadIdx.x == 0) off[n] = carry_s;
}
__global__ void fill_eid_k(const int* __restrict__ recv,
                           const int* __restrict__ send,
                           int* pos, int* eid, int* sperm, int e)
{
    int i = blockIdx.x * blockDim.x + threadIdx.x;
    if (i < e) {
        int p = atomicAdd(&pos[recv[i]], 1);
        eid[p] = i;
        sperm[p] = send[i];
    }
}

// ---------------- gather: TP + segment sum (receiver-sorted inputs) ---------
__global__ void gather_k(const float* __restrict__ h,
                         const float* __restrict__ tpw,
                         const float* __restrict__ ys,
                         const int* __restrict__ sperm,
                         const int* __restrict__ off,
                         bf16* __restrict__ msgh, bf16* __restrict__ msgl)
{
    int n = blockIdx.x;
    int c = threadIdx.x;   // 128 threads, one per channel
    float ar[9], ai[9];
#pragma unroll
    for (int j = 0; j < 9; j++) { ar[j] = 0.f; ai[j] = 0.f; }

    int e0 = __ldg(&off[n]);
    int e1 = __ldg(&off[n + 1]);
    for (int p = e0; p < e1; p++) {
        int s = __ldg(&sperm[p]);
        float hc = h[(size_t)s * CC + c];      // L2-resident (5 MB)
        const float* tw = tpw + (size_t)p * 384;   // sequential
        float xw0 = hc * tw[c];
        float xw1 = hc * tw[128 + c];
        float xw2 = hc * tw[256 + c];
        const float* er = ys + (size_t)p * 18;     // sequential
        const float* ei = er + 9;
        ar[0] += xw0 * __ldg(&er[0]);
        ai[0] += xw0 * __ldg(&ei[0]);
#pragma unroll
        for (int m = 0; m < 3; m++) {
            ar[1 + m] += xw1 * __ldg(&er[1 + m]);
            ai[1 + m] += xw1 * __ldg(&ei[1 + m]);
        }
#pragma unroll
        for (int m = 0; m < 5; m++) {
            ar[4 + m] += xw2 * __ldg(&er[4 + m]);
            ai[4 + m] += xw2 * __ldg(&ei[4 + m]);
        }
    }

    // per-l contiguous layout, split to bf16 hi/lo
#pragma unroll
    for (int z = 0; z < 2; z++) {
        const float* a = z ? ai : ar;
        bf16* mh = msgh + (size_t)z * ZSZ;
        bf16* ml = msgl + (size_t)z * ZSZ;
        bf16 hi, lo;
        split1(a[0], hi, lo);
        mh[L0OFF + (size_t)n * CC + c] = hi;
        ml[L0OFF + (size_t)n * CC + c] = lo;
#pragma unroll
        for (int m = 0; m < 3; m++) {
            split1(a[1 + m], hi, lo);
            mh[L1OFF + ((size_t)n * 3 + m) * CC + c] = hi;
            ml[L1OFF + ((size_t)n * 3 + m) * CC + c] = lo;
        }
#pragma unroll
        for (int m = 0; m < 5; m++) {
            split1(a[4 + m], hi, lo);
            mh[L2OFF + ((size_t)n * 5 + m) * CC + c] = hi;
            ml[L2OFF + ((size_t)n * 5 + m) * CC + c] = lo;
        }
    }
}

// ---------------- launch ----------------------------------------------------
static inline float* symf(const void* sym)
{
    void* p = nullptr;
    cudaGetSymbolAddress(&p, sym);
    return (float*)p;
}
static inline bf16* symb(const void* sym)
{
    void* p = nullptr;
    cudaGetSymbolAddress(&p, sym);
    return (bf16*)p;
}
static inline int* symi(const void* sym)
{
    void* p = nullptr;
    cudaGetSymbolAddress(&p, sym);
    return (int*)p;
}

extern "C" void kernel_launch(void* const* d_in, const int* in_sizes, int n_in,
                              void* d_out, int out_size)
{
    const float* node_attrs = (const float*)d_in[0];
    const float* node_feats = (const float*)d_in[1];
    const float* yr         = (const float*)d_in[2];
    const float* yi         = (const float*)d_in[3];
    const float* edge_feats = (const float*)d_in[4];
    const int*   edge_index = (const int*)d_in[5];
    const float* W_up   = (const float*)d_in[6];
    const float* W_skip = (const float*)d_in[7];
    const float* W1     = (const float*)d_in[8];
    const float* W2     = (const float*)d_in[9];
    const float* W3     = (const float*)d_in[10];
    const float* W4     = (const float*)d_in[11];
    const float* Wl[3]  = { (const float*)d_in[12], (const float*)d_in[13],
                            (const float*)d_in[14] };
    float* out = (float*)d_out;

    static int smem_set = 0;
    if (!smem_set) {
        cudaFuncSetAttribute(tc_gemm_k<1>,
                             cudaFuncAttributeMaxDynamicSharedMemorySize, S_TOT1);
        cudaFuncSetAttribute(irr_gemm_k,
                             cudaFuncAttributeMaxDynamicSharedMemorySize, S_TOT1);
        cudaFuncSetAttribute(mlp_fused_k,
                             cudaFuncAttributeMaxDynamicSharedMemorySize, S_MLP);
        smem_set = 1;
    }

    float* hh   = symf(g_h);
    float* tpw  = symf(g_tpw);
    float* ys   = symf(g_ys);
    float* tmp  = symf(g_tmp);
    bf16* nfh = symb(g_nfh); bf16* nfl = symb(g_nfl);
    bf16* yh  = symb(g_yh);  bf16* yl  = symb(g_yl);
    bf16* msgh = symb(g_msgh); bf16* msgl = symb(g_msgl);
    bf16* wth = symb(g_wth); bf16* wtl = symb(g_wtl);
    int* deg = symi(g_deg);
    int* off = symi(g_off);
    int* pos = symi(g_pos);
    int* eid = symi(g_eid);
    int* sperm = symi(g_sperm);

    const int* recv = edge_index + EE;
    const int* send = edge_index;

    // 1
    yprep_k<<<NN, 256>>>(node_feats, node_attrs, yh, yl);
    // 2
    transpose_all_k<<<1040, 256>>>(W_up, W_skip, W1, W2, W3, W4,
                                   Wl[0], Wl[1], Wl[2], wth, wtl);
    // 3: zero sc region (split-K accumulates atomically)
    zero_f_k<<<(NN * CC + 255) / 256, 256>>>(out + SC_OFF, NN * CC);
    // 4: sc = y @ W_skip, split-K x4 (profiled launch)
    {
        dim3 grid(2, (NN + 127) / 128, 4);
        tc_gemm_k<1><<<grid, 256, S_TOT1>>>(yh, yl, wth + WSK_T, wtl + WSK_T,
                                            out + SC_OFF, nullptr, nullptr,
                                            CC, CC * AA, CC * AA,
                                            NN, (CC * AA) / 4, 0, 1);
    }
    // node feats split (for h GEMM)
    conv_split_k<<<1024, 256>>>(node_feats, nfh, nfl, NN, CC, CC);
    // CSR
    zero_deg_k<<<(NN + 255) / 256, 256>>>(deg, NN);
    count_deg_k<<<(EE + 255) / 256, 256>>>(recv, deg, EE);
    scan_k<<<1, 1024>>>(deg, off, pos, NN);
    fill_eid_k<<<(EE + 255) / 256, 256>>>(recv, send, pos, eid, sperm, EE);
    // sorted SH pack
    pack_ys_k<<<2048, 256>>>(yr, yi, eid, ys);
    // fused edge MLP -> tpw (receiver-sorted)
    mlp_fused_k<<<EE / 256, 256, S_MLP>>>(edge_feats, eid, wth, wtl, tpw);
    // h = node_feats @ W_up
    {
        dim3 grid(2, (NN + 127) / 128, 1);
        tc_gemm_k<1><<<grid, 256, S_TOT1>>>(nfh, nfl, wth + WUP_T, wtl + WUP_T,
                                            hh, nullptr, nullptr,
                                            CC, CC, CC, NN, CC, 0, 0);
    }
    // tensor product + segment sum
    gather_k<<<NN, 128>>>(hh, tpw, ys, sperm, off, msgh, msgl);
    // all 6 irreps GEMMs in one launch
    irr_gemm_k<<<dim3(2, 391, 6), 256, S_TOT1>>>(msgh, msgl, wth, wtl, tmp);
    // merge tmp -> out (coalesced both sides)
    merge_k<<<dim3(NN, 2), 128>>>(tmp, out);
}